// round 15
// baseline (speedup 1.0000x reference)
#include <cuda_runtime.h>
#include <cstdint>
#include <math.h>

// ---------------- problem constants ----------------
#define BB     2
#define SS     2048
#define DD     2048
#define HH     8
#define HDIM   256
#define HALF   128           // HDIM/2
#define NQKV   2560          // 2048 q + 256 k + 256 v
#define MTOT   4096          // B*S
#define WINM1  1023
#define SCALE  0.0625f       // 1/sqrt(256)

// ---------------- scratch (device globals; no allocation) ----------------
__device__ float g_q[BB * HH * SS * HDIM];     // [B,H,S,HD]
__device__ float g_k[BB * SS * HDIM];          // [B,S,HD]
__device__ float g_v[BB * SS * HDIM];          // [B,S,HD]
__device__ float g_attn[BB * SS * HH * HDIM];  // [B,S,H*HD]
__device__ float g_ct[BB * SS * HALF];
__device__ float g_st[BB * SS * HALF];

// ---------------- cp.async helpers ----------------
__device__ __forceinline__ void cp_async16(uint32_t saddr, const void* gptr) {
    asm volatile("cp.async.cg.shared.global [%0], [%1], 16;" :: "r"(saddr), "l"(gptr));
}
__device__ __forceinline__ void cp_async_commit() { asm volatile("cp.async.commit_group;"); }
__device__ __forceinline__ void cp_async_wait0()  { asm volatile("cp.async.wait_group 0;"); }

// ---------------- RoPE table ----------------
__global__ void rope_table_kernel(const int* __restrict__ pos,
                                  float* __restrict__ ct, float* __restrict__ st) {
    int idx = blockIdx.x * 256 + threadIdx.x;      // B*S*HALF total
    if (idx >= BB * SS * HALF) return;
    int j  = idx & (HALF - 1);
    int bs = idx >> 7;
    int p  = pos[bs];
    double inv  = pow(10000.0, -(double)j / 128.0);
    float  invf = (float)inv;                       // fp32 inv_freq (matches reference dtype)
    float  angf = (float)p * invf;                  // fp32-rounded angle, like jax
    double a    = (double)angf;
    ct[idx] = (float)cos(a);
    st[idx] = (float)sin(a);
}

// ---------------- RoPE apply (in-place on q and k) ----------------
__global__ void rope_apply_kernel(float* __restrict__ q, float* __restrict__ k,
                                  const float* __restrict__ ct, const float* __restrict__ st) {
    const int QTOT = BB * HH * SS * HALF;          // 4,194,304
    const int KTOT = BB * SS * HALF;               //   524,288
    int idx = blockIdx.x * 256 + threadIdx.x;
    if (idx < QTOT) {
        int j  = idx & (HALF - 1);
        int s  = (idx >> 7) & (SS - 1);
        int bh = idx >> 18;
        int b  = bh >> 3;
        float* p = q + ((size_t)bh * SS + s) * HDIM;
        int ti = (b * SS + s) * HALF + j;
        float c = ct[ti], sn = st[ti];
        float x1 = p[j], x2 = p[j + HALF];
        p[j]        = x1 * c - x2 * sn;
        p[j + HALF] = x2 * c + x1 * sn;
    } else {
        int r = idx - QTOT;
        if (r < KTOT) {
            int j = r & (HALF - 1);
            int s = (r >> 7) & (SS - 1);
            int b = r >> 18;
            float* p = k + ((size_t)(b * SS + s)) * HDIM;
            float c = ct[r], sn = st[r];
            float x1 = p[j], x2 = p[j + HALF];
            p[j]        = x1 * c - x2 * sn;
            p[j + HALF] = x2 * c + x1 * sn;
        }
    }
}

// ---------------- 128x128x8 fp32 GEMM: C = A @ W^T ----------------
// mode 0: B rows from W0[n][k], write C0[m*N + n]
// mode 1: fused QKV: n<2048 -> Wq->g_q scatter ([B,H,S,HD]); n<2304 -> Wk->g_k; else Wv->g_v
__global__ void __launch_bounds__(256, 2)
gemm_kernel(const float* __restrict__ A,
            const float* __restrict__ W0, const float* __restrict__ W1, const float* __restrict__ W2,
            float* __restrict__ C0, float* __restrict__ C1, float* __restrict__ C2,
            int M, int N, int K, int mode) {
    __shared__ float As[8][132];
    __shared__ float Bs[8][132];

    const int t  = threadIdx.x;
    const int tx = t & 15, ty = t >> 4;
    const int m0 = blockIdx.y << 7;
    const int n0 = blockIdx.x << 7;
    const int lr = t >> 1;             // 0..127
    const int lk = (t & 1) << 2;       // 0 or 4

    const float* aptr = A + (size_t)(m0 + lr) * K + lk;
    const int gn = n0 + lr;
    const float* bptr;
    if (mode == 0) {
        bptr = W0 + (size_t)gn * K + lk;
    } else {
        if (gn < 2048)      bptr = W0 + (size_t)gn * 2048 + lk;
        else if (gn < 2304) bptr = W1 + (size_t)(gn - 2048) * 2048 + lk;
        else                bptr = W2 + (size_t)(gn - 2304) * 2048 + lk;
    }

    float4 ar = *(const float4*)aptr;
    float4 br = *(const float4*)bptr;

    float acc[8][8];
#pragma unroll
    for (int i = 0; i < 8; ++i)
#pragma unroll
        for (int j = 0; j < 8; ++j) acc[i][j] = 0.f;

    for (int kt = 0; kt < K; kt += 8) {
        As[lk + 0][lr] = ar.x; As[lk + 1][lr] = ar.y; As[lk + 2][lr] = ar.z; As[lk + 3][lr] = ar.w;
        Bs[lk + 0][lr] = br.x; Bs[lk + 1][lr] = br.y; Bs[lk + 2][lr] = br.z; Bs[lk + 3][lr] = br.w;
        __syncthreads();
        if (kt + 8 < K) {
            ar = *(const float4*)(aptr + kt + 8);
            br = *(const float4*)(bptr + kt + 8);
        }
#pragma unroll
        for (int kk = 0; kk < 8; ++kk) {
            float4 a0 = *(const float4*)&As[kk][ty << 2];
            float4 a1 = *(const float4*)&As[kk][64 + (ty << 2)];
            float4 b0 = *(const float4*)&Bs[kk][tx << 2];
            float4 b1 = *(const float4*)&Bs[kk][64 + (tx << 2)];
            float av[8] = {a0.x, a0.y, a0.z, a0.w, a1.x, a1.y, a1.z, a1.w};
            float bv[8] = {b0.x, b0.y, b0.z, b0.w, b1.x, b1.y, b1.z, b1.w};
#pragma unroll
            for (int i = 0; i < 8; ++i)
#pragma unroll
                for (int j = 0; j < 8; ++j) acc[i][j] += av[i] * bv[j];
        }
        __syncthreads();
    }

    // epilogue
#pragma unroll
    for (int ih = 0; ih < 2; ++ih)
#pragma unroll
        for (int i = 0; i < 4; ++i) {
            int m  = m0 + ih * 64 + (ty << 2) + i;
            int bb = m >> 11;
            int s  = m & (SS - 1);
#pragma unroll
            for (int jh = 0; jh < 2; ++jh) {
                int n = n0 + jh * 64 + (tx << 2);
                float4 v = make_float4(acc[ih * 4 + i][jh * 4 + 0], acc[ih * 4 + i][jh * 4 + 1],
                                       acc[ih * 4 + i][jh * 4 + 2], acc[ih * 4 + i][jh * 4 + 3]);
                if (mode == 0) {
                    *(float4*)(C0 + (size_t)m * N + n) = v;
                } else if (n < 2048) {
                    int hh = n >> 8, d = n & 255;
                    *(float4*)(C0 + (((size_t)(bb * HH + hh)) * SS + s) * HDIM + d) = v;
                } else if (n < 2304) {
                    *(float4*)(C1 + ((size_t)(bb * SS + s)) * HDIM + (n - 2048)) = v;
                } else {
                    *(float4*)(C2 + ((size_t)(bb * SS + s)) * HDIM + (n - 2304)) = v;
                }
            }
        }
}

// ---------------- fp32 sliding-window flash attention ----------------
// block = (b, h, 64 q-rows); 256 threads (16x16). smem: Qs[256][68] Ks[32][68] Ps[64][68] Vs[64][260]
#define QS_LD 68
#define VS_LD 260
#define SM_KS (256 * QS_LD)
#define SM_PS (SM_KS + 32 * QS_LD)
#define SM_VS (SM_PS + 64 * QS_LD)
#define ATT_SMEM ((SM_VS + 64 * VS_LD) * 4)

__global__ void __launch_bounds__(256, 1)
attn_kernel(const float* __restrict__ Q, const float* __restrict__ Kg,
            const float* __restrict__ Vg, float* __restrict__ O) {
    extern __shared__ float sm[];
    float* Qs = sm;
    float* Ks = sm + SM_KS;
    float* Ps = sm + SM_PS;
    float* Vs = sm + SM_VS;
    const uint32_t vs_base = (uint32_t)__cvta_generic_to_shared(Vs);

    const int t  = threadIdx.x;
    const int tx = t & 15, ty = t >> 4;
    const int q0 = blockIdx.x << 6;
    const int h  = blockIdx.y;
    const int b  = blockIdx.z;

    const float* Qg = Q + ((size_t)((b * HH + h) * SS + q0)) * HDIM;
    const float* Kb = Kg + (size_t)b * SS * HDIM;
    const float* Vb = Vg + (size_t)b * SS * HDIM;

    // load Q tile transposed: Qs[d][m]
    {
        const int row = t & 63;
        const int db  = (t >> 6) << 2;
#pragma unroll
        for (int p = 0; p < 16; ++p) {
            const int d = db + (p << 4);
            float4 v = *(const float4*)(Qg + row * HDIM + d);
            Qs[(d + 0) * QS_LD + row] = v.x;
            Qs[(d + 1) * QS_LD + row] = v.y;
            Qs[(d + 2) * QS_LD + row] = v.z;
            Qs[(d + 3) * QS_LD + row] = v.w;
        }
    }

    float o[4][4][4];
#pragma unroll
    for (int c = 0; c < 4; ++c)
#pragma unroll
        for (int i = 0; i < 4; ++i)
#pragma unroll
            for (int j = 0; j < 4; ++j) o[c][i][j] = 0.f;
    float mrow[4], lrow[4];
#pragma unroll
    for (int i = 0; i < 4; ++i) { mrow[i] = -1e30f; lrow[i] = 0.f; }

    int kb_lo = q0 - WINM1; if (kb_lo < 0) kb_lo = 0; kb_lo &= ~63;

    for (int kb = kb_lo; kb <= q0 + 63; kb += 64) {
        __syncthreads();   // Qs ready (first iter); Vs/Ps free (later iters)

        // async V tile: Vs[key][d]
#pragma unroll
        for (int p = 0; p < 16; ++p) {
            int e4  = (p << 8) + t;
            int key = e4 >> 6;
            int d   = (e4 & 63) << 2;
            cp_async16(vs_base + (uint32_t)((key * VS_LD + d) << 2),
                       Vb + (size_t)(kb + key) * HDIM + d);
        }
        cp_async_commit();

        // ---- scores: sc[4][4] over d in 8 chunks of 32 ----
        float sc[4][4];
#pragma unroll
        for (int i = 0; i < 4; ++i)
#pragma unroll
            for (int j = 0; j < 4; ++j) sc[i][j] = 0.f;

        const int krow = t & 63;
        const int kdb  = (t >> 6) << 2;
        const float* kptr = Kb + (size_t)(kb + krow) * HDIM + kdb;
        float4 kr0 = *(const float4*)(kptr);
        float4 kr1 = *(const float4*)(kptr + 16);

#pragma unroll
        for (int dc = 0; dc < 8; ++dc) {
            Ks[(kdb + 0)  * QS_LD + krow] = kr0.x;
            Ks[(kdb + 1)  * QS_LD + krow] = kr0.y;
            Ks[(kdb + 2)  * QS_LD + krow] = kr0.z;
            Ks[(kdb + 3)  * QS_LD + krow] = kr0.w;
            Ks[(kdb + 16) * QS_LD + krow] = kr1.x;
            Ks[(kdb + 17) * QS_LD + krow] = kr1.y;
            Ks[(kdb + 18) * QS_LD + krow] = kr1.z;
            Ks[(kdb + 19) * QS_LD + krow] = kr1.w;
            __syncthreads();
            if (dc < 7) {
                kr0 = *(const float4*)(kptr + (dc + 1) * 32);
                kr1 = *(const float4*)(kptr + (dc + 1) * 32 + 16);
            }
#pragma unroll
            for (int dd = 0; dd < 32; ++dd) {
                float4 a  = *(const float4*)(Qs + (dc * 32 + dd) * QS_LD + (ty << 2));
                float4 bb = *(const float4*)(Ks + dd * QS_LD + (tx << 2));
                float av[4] = {a.x, a.y, a.z, a.w};
                float bv[4] = {bb.x, bb.y, bb.z, bb.w};
#pragma unroll
                for (int i = 0; i < 4; ++i)
#pragma unroll
                    for (int j = 0; j < 4; ++j) sc[i][j] += av[i] * bv[j];
            }
            __syncthreads();
        }

        // ---- mask + online softmax ----
        float pv[4][4];
        float alpha[4];
#pragma unroll
        for (int i = 0; i < 4; ++i) {
            const int qr = q0 + (ty << 2) + i;
            float s4[4];
            float mloc = -1e30f;
#pragma unroll
            for (int j = 0; j < 4; ++j) {
                int kc = kb + (tx << 2) + j;
                bool ok = (kc <= qr) && (kc >= qr - WINM1);
                float s = ok ? sc[i][j] * SCALE : -1e30f;
                s4[j] = s;
                mloc = fmaxf(mloc, s);
            }
#pragma unroll
            for (int off = 1; off < 16; off <<= 1)
                mloc = fmaxf(mloc, __shfl_xor_sync(0xffffffffu, mloc, off));
            float mnew = fmaxf(mrow[i], mloc);
            alpha[i] = __expf(mrow[i] - mnew);
            mrow[i]  = mnew;
            float psum = 0.f;
#pragma unroll
            for (int j = 0; j < 4; ++j) {
                int kc = kb + (tx << 2) + j;
                bool ok = (kc <= qr) && (kc >= qr - WINM1);
                float p = ok ? __expf(s4[j] - mnew) : 0.f;
                pv[i][j] = p;
                psum += p;
            }
#pragma unroll
            for (int off = 1; off < 16; off <<= 1)
                psum += __shfl_xor_sync(0xffffffffu, psum, off);
            lrow[i] = lrow[i] * alpha[i] + psum;
        }

        // store P (row-major [m][kk]) and rescale O
#pragma unroll
        for (int i = 0; i < 4; ++i)
            *(float4*)(Ps + ((ty << 2) + i) * QS_LD + (tx << 2)) =
                make_float4(pv[i][0], pv[i][1], pv[i][2], pv[i][3]);
#pragma unroll
        for (int c = 0; c < 4; ++c)
#pragma unroll
            for (int i = 0; i < 4; ++i)
#pragma unroll
                for (int j = 0; j < 4; ++j) o[c][i][j] *= alpha[i];

        cp_async_wait0();
        __syncthreads();

        // ---- PV: O[m][d] += P[m][kk] * V[kk][d] ----
#pragma unroll 4
        for (int kk = 0; kk < 64; ++kk) {
            float p0 = Ps[((ty << 2) + 0) * QS_LD + kk];
            float p1 = Ps[((ty << 2) + 1) * QS_LD + kk];
            float p2 = Ps[((ty << 2) + 2) * QS_LD + kk];
            float p3 = Ps[((ty << 2) + 3) * QS_LD + kk];
#pragma unroll
            for (int c = 0; c < 4; ++c) {
                float4 v = *(const float4*)(Vs + kk * VS_LD + (c << 6) + (tx << 2));
                o[c][0][0] += p0 * v.x; o[c][0][1] += p0 * v.y; o[c][0][2] += p0 * v.z; o[c][0][3] += p0 * v.w;
                o[c][1][0] += p1 * v.x; o[c][1][1] += p1 * v.y; o[c][1][2] += p1 * v.z; o[c][1][3] += p1 * v.w;
                o[c][2][0] += p2 * v.x; o[c][2][1] += p2 * v.y; o[c][2][2] += p2 * v.z; o[c][2][3] += p2 * v.w;
                o[c][3][0] += p3 * v.x; o[c][3][1] += p3 * v.y; o[c][3][2] += p3 * v.z; o[c][3][3] += p3 * v.w;
            }
        }
    }

    // ---- epilogue: O[b][s][h*HD + d] ----
#pragma unroll
    for (int i = 0; i < 4; ++i) {
        float inv = 1.0f / lrow[i];
        size_t rowbase = ((size_t)(b * SS + q0 + (ty << 2) + i)) * (HH * HDIM) + h * HDIM;
#pragma unroll
        for (int c = 0; c < 4; ++c) {
            float4 v = make_float4(o[c][i][0] * inv, o[c][i][1] * inv,
                                   o[c][i][2] * inv, o[c][i][3] * inv);
            *(float4*)(O + rowbase + (c << 6) + (tx << 2)) = v;
        }
    }
}

// ---------------- launcher ----------------
extern "C" void kernel_launch(void* const* d_in, const int* in_sizes, int n_in,
                              void* d_out, int out_size) {
    const float* hidden = (const float*)d_in[0];
    // d_in[1] = attention_mask (pure causal; realized analytically)
    const int*   pos    = (const int*)d_in[2];
    const float* Wq     = (const float*)d_in[3];
    const float* Wk     = (const float*)d_in[4];
    const float* Wv     = (const float*)d_in[5];
    const float* Wo     = (const float*)d_in[6];
    float*       out    = (float*)d_out;

    float *qb, *kb, *vb, *ab, *ct, *st;
    cudaGetSymbolAddress((void**)&qb, g_q);
    cudaGetSymbolAddress((void**)&kb, g_k);
    cudaGetSymbolAddress((void**)&vb, g_v);
    cudaGetSymbolAddress((void**)&ab, g_attn);
    cudaGetSymbolAddress((void**)&ct, g_ct);
    cudaGetSymbolAddress((void**)&st, g_st);

    // 1. RoPE tables
    rope_table_kernel<<<(BB * SS * HALF) / 256, 256>>>(pos, ct, st);

    // 2. fused QKV projection
    gemm_kernel<<<dim3(NQKV / 128, MTOT / 128), 256>>>(
        hidden, Wq, Wk, Wv, qb, kb, vb, MTOT, NQKV, DD, 1);

    // 3. RoPE apply (q + k)
    {
        int total = BB * HH * SS * HALF + BB * SS * HALF;
        rope_apply_kernel<<<(total + 255) / 256, 256>>>(qb, kb, ct, st);
    }

    // 4. sliding-window flash attention
    cudaFuncSetAttribute(attn_kernel, cudaFuncAttributeMaxDynamicSharedMemorySize, ATT_SMEM);
    attn_kernel<<<dim3(SS / 64, HH, BB), 256, ATT_SMEM>>>(qb, kb, vb, ab);

    // 5. output projection
    gemm_kernel<<<dim3(DD / 128, MTOT / 128), 256>>>(
        ab, Wo, nullptr, nullptr, out, nullptr, nullptr, MTOT, DD, HH * HDIM, 0);
}